// round 3
// baseline (speedup 1.0000x reference)
#include <cuda_runtime.h>
#include <math.h>

#define M_ROWS 512
#define K_COMP 8
#define B_PTS  4096
#define B_QTR  1024
#define PHI_DIM 120
#define Z_COLS 80
#define LOG2PI_F 1.8378770664093453f
#define LOG2E_F  1.4426950408889634f

// Scratch (device globals — no allocation allowed)
__device__ float g_z[M_ROWS * Z_COLS];          // columns 0..71 (mu, logL, pi)
__device__ float g_resp[4][M_ROWS][K_COMP];     // partial resp sums per quarter

// ---- packed f32x2 helpers -------------------------------------------------
typedef unsigned long long u64;

__device__ __forceinline__ u64 pk2(float lo, float hi) {
    u64 r; asm("mov.b64 %0, {%1, %2};" : "=l"(r) : "f"(lo), "f"(hi)); return r;
}
__device__ __forceinline__ void unpk2(u64 v, float& lo, float& hi) {
    asm("mov.b64 {%0, %1}, %2;" : "=f"(lo), "=f"(hi) : "l"(v));
}
__device__ __forceinline__ u64 fma2(u64 a, u64 b, u64 c) {
    u64 d; asm("fma.rn.f32x2 %0, %1, %2, %3;" : "=l"(d) : "l"(a), "l"(b), "l"(c)); return d;
}
__device__ __forceinline__ u64 mul2(u64 a, u64 b) {
    u64 d; asm("mul.rn.f32x2 %0, %1, %2;" : "=l"(d) : "l"(a), "l"(b)); return d;
}
__device__ __forceinline__ float ex2f(float x) {
    float r; asm("ex2.approx.f32 %0, %1;" : "=f"(r) : "f"(x)); return r;
}

// ---------------------------------------------------------------------------
// Main kernel: fused prep + responsibility accumulation.
// grid = 2048: block bx -> m = bx>>2, quarter = bx&3. 128 threads.
// ---------------------------------------------------------------------------
__global__ void __launch_bounds__(128, 3) gmm_main(const float* __restrict__ phi,
                                                   const float4* __restrict__ X) {
    const int m = blockIdx.x >> 2;
    const int q = blockIdx.x & 3;
    const int tid = threadIdx.x;

    // Per k (log2 domain): rs0..rs3, c0..c3, s10n,s20n,s21n,s30n,s31n,s32n, ck2
    __shared__ float sp[K_COMP][15];

    if (tid < K_COMP) {
        const int k = tid;
        const float* pm = phi + m * PHI_DIM;

        float mx = -INFINITY;
        #pragma unroll
        for (int j = 0; j < K_COMP; j++) mx = fmaxf(mx, pm[j]);
        float s = 0.f;
        #pragma unroll
        for (int j = 0; j < K_COMP; j++) s += __expf(pm[j] - mx);
        float pik = __expf(pm[k] - mx) / s;

        float mu0 = pm[8 + k * 4 + 0];
        float mu1 = pm[8 + k * 4 + 1];
        float mu2 = pm[8 + k * 4 + 2];
        float mu3 = pm[8 + k * 4 + 3];

        const float* lv = pm + 40 + k * 10;
        float L00 = lv[0], L10 = lv[1], L11 = lv[2], L20 = lv[3], L21 = lv[4];
        float L22 = lv[5], L30 = lv[6], L31 = lv[7], L32 = lv[8], L33 = lv[9];

        float r0 = 1.0f / L00, r1 = 1.0f / L11, r2 = 1.0f / L22, r3 = 1.0f / L33;
        const float sc = sqrtf(0.5f * LOG2E_F);   // alpha scaled so lj is in log2 units
        float rs0 = r0 * sc, rs1 = r1 * sc, rs2 = r2 * sc, rs3 = r3 * sc;

        sp[k][0] = rs0;  sp[k][1] = rs1;  sp[k][2] = rs2;  sp[k][3] = rs3;
        sp[k][4] = -mu0 * rs0;
        sp[k][5] = -mu1 * rs1;
        sp[k][6] = -mu2 * rs2;
        sp[k][7] = -mu3 * rs3;
        sp[k][8]  = -(L10 * r1);
        sp[k][9]  = -(L20 * r2);
        sp[k][10] = -(L21 * r2);
        sp[k][11] = -(L30 * r3);
        sp[k][12] = -(L31 * r3);
        sp[k][13] = -(L32 * r3);

        float ld0 = __logf(fmaxf(fabsf(L00), 1e-8f));
        float ld1 = __logf(fmaxf(fabsf(L11), 1e-8f));
        float ld2 = __logf(fmaxf(fabsf(L22), 1e-8f));
        float ld3 = __logf(fmaxf(fabsf(L33), 1e-8f));
        float log_det = 2.0f * (ld0 + ld1 + ld2 + ld3);
        float ck = __logf(fmaxf(pik, 1e-8f)) - 0.5f * (4.0f * LOG2PI_F + log_det);
        sp[k][14] = ck * LOG2E_F;   // log2 domain

        if (q == 0) {
            float* Z = g_z + m * Z_COLS;
            Z[k * 4 + 0] = mu0;  Z[k * 4 + 1] = mu1;
            Z[k * 4 + 2] = mu2;  Z[k * 4 + 3] = mu3;
            Z[32 + k * 4 + 0] = __logf(fmaxf(fabsf(L00), 1e-6f));
            Z[32 + k * 4 + 1] = __logf(fmaxf(fabsf(L11), 1e-6f));
            Z[32 + k * 4 + 2] = __logf(fmaxf(fabsf(L22), 1e-6f));
            Z[32 + k * 4 + 3] = __logf(fmaxf(fabsf(L33), 1e-6f));
            Z[64 + k] = pik;
        }
    }
    __syncthreads();

    // ---- pack params: pair p covers k = 2p (lo), 2p+1 (hi) ----
    u64 prs0[4], prs1[4], prs2[4], prs3[4];
    u64 pc0[4], pc1[4], pc2[4], pc3[4];
    u64 ps10[4], ps20[4], ps21[4], ps30[4], ps31[4], ps32[4], pck[4];
    #pragma unroll
    for (int p = 0; p < 4; p++) {
        int a = 2 * p, b = 2 * p + 1;
        prs0[p] = pk2(sp[a][0], sp[b][0]);
        prs1[p] = pk2(sp[a][1], sp[b][1]);
        prs2[p] = pk2(sp[a][2], sp[b][2]);
        prs3[p] = pk2(sp[a][3], sp[b][3]);
        pc0[p]  = pk2(sp[a][4], sp[b][4]);
        pc1[p]  = pk2(sp[a][5], sp[b][5]);
        pc2[p]  = pk2(sp[a][6], sp[b][6]);
        pc3[p]  = pk2(sp[a][7], sp[b][7]);
        ps10[p] = pk2(sp[a][8], sp[b][8]);
        ps20[p] = pk2(sp[a][9], sp[b][9]);
        ps21[p] = pk2(sp[a][10], sp[b][10]);
        ps30[p] = pk2(sp[a][11], sp[b][11]);
        ps31[p] = pk2(sp[a][12], sp[b][12]);
        ps32[p] = pk2(sp[a][13], sp[b][13]);
        pck[p]  = pk2(sp[a][14], sp[b][14]);
    }
    const u64 NEG1 = pk2(-1.0f, -1.0f);

    float acc[K_COMP];
    #pragma unroll
    for (int k = 0; k < K_COMP; k++) acc[k] = 0.f;

    const int i0 = q * B_QTR;
    for (int i = i0 + tid; i < i0 + B_QTR; i += 128) {
        float4 x = X[i];
        u64 xp0 = pk2(x.x, x.x);
        u64 xp1 = pk2(x.y, x.y);
        u64 xp2 = pk2(x.z, x.z);
        u64 xp3 = pk2(x.w, x.w);

        u64 ljp[4];
        #pragma unroll
        for (int p = 0; p < 4; p++) {
            u64 a0 = fma2(xp0, prs0[p], pc0[p]);
            u64 a1 = fma2(xp1, prs1[p], pc1[p]);
            a1 = fma2(a0, ps10[p], a1);
            u64 a2 = fma2(xp2, prs2[p], pc2[p]);
            a2 = fma2(a0, ps20[p], a2);
            a2 = fma2(a1, ps21[p], a2);
            u64 a3 = fma2(xp3, prs3[p], pc3[p]);
            a3 = fma2(a0, ps30[p], a3);
            a3 = fma2(a1, ps31[p], a3);
            a3 = fma2(a2, ps32[p], a3);
            u64 qq = mul2(a0, a0);
            qq = fma2(a1, a1, qq);
            qq = fma2(a2, a2, qq);
            qq = fma2(a3, a3, qq);
            ljp[p] = fma2(qq, NEG1, pck[p]);   // ck2 - sum(a'^2)  (log2 units)
        }

        float lj[K_COMP];
        #pragma unroll
        for (int p = 0; p < 4; p++) unpk2(ljp[p], lj[2 * p], lj[2 * p + 1]);

        float mx = fmaxf(fmaxf(fmaxf(lj[0], lj[1]), fmaxf(lj[2], lj[3])),
                         fmaxf(fmaxf(lj[4], lj[5]), fmaxf(lj[6], lj[7])));
        u64 mxp = pk2(mx, mx);

        float ex[K_COMP]; float s = 0.f;
        #pragma unroll
        for (int p = 0; p < 4; p++) {
            u64 d = fma2(mxp, NEG1, ljp[p]);   // lj - mx
            float dl, dh;
            unpk2(d, dl, dh);
            ex[2 * p]     = ex2f(dl);
            ex[2 * p + 1] = ex2f(dh);
            s += ex[2 * p] + ex[2 * p + 1];
        }
        float inv = __fdividef(1.0f, s);
        #pragma unroll
        for (int k = 0; k < K_COMP; k++) acc[k] = __fmaf_rn(ex[k], inv, acc[k]);
    }

    // ---- block reduce 4 warps ----
    __shared__ float sred[4][K_COMP];
    unsigned wid = tid >> 5, lane = tid & 31;
    #pragma unroll
    for (int k = 0; k < K_COMP; k++) {
        float v = acc[k];
        v += __shfl_down_sync(0xffffffffu, v, 16);
        v += __shfl_down_sync(0xffffffffu, v, 8);
        v += __shfl_down_sync(0xffffffffu, v, 4);
        v += __shfl_down_sync(0xffffffffu, v, 2);
        v += __shfl_down_sync(0xffffffffu, v, 1);
        if (lane == 0) sred[wid][k] = v;
    }
    __syncthreads();
    if (tid < K_COMP) {
        g_resp[q][m][tid] = sred[0][tid] + sred[1][tid] + sred[2][tid] + sred[3][tid];
    }
}

// ---------------------------------------------------------------------------
// Standardization: warp-per-column. 20 blocks x 128 threads (4 warps = 4 cols).
// ---------------------------------------------------------------------------
__global__ void __launch_bounds__(128, 8) gmm_norm(float* __restrict__ out) {
    const int c = blockIdx.x * 4 + (threadIdx.x >> 5);
    const int lane = threadIdx.x & 31;

    float v[16];
    if (c < 72) {
        #pragma unroll
        for (int j = 0; j < 16; j++) {
            int r = lane + 32 * j;
            v[j] = g_z[r * Z_COLS + c];
        }
    } else {
        int k = c - 72;
        #pragma unroll
        for (int j = 0; j < 16; j++) {
            int r = lane + 32 * j;
            v[j] = (g_resp[0][r][k] + g_resp[1][r][k] +
                    g_resp[2][r][k] + g_resp[3][r][k]) * (1.0f / (float)B_PTS);
        }
    }

    float s = 0.f;
    #pragma unroll
    for (int j = 0; j < 16; j++) s += v[j];
    s += __shfl_down_sync(0xffffffffu, s, 16);
    s += __shfl_down_sync(0xffffffffu, s, 8);
    s += __shfl_down_sync(0xffffffffu, s, 4);
    s += __shfl_down_sync(0xffffffffu, s, 2);
    s += __shfl_down_sync(0xffffffffu, s, 1);
    float mean = __shfl_sync(0xffffffffu, s, 0) * (1.0f / (float)M_ROWS);

    float qsum = 0.f;
    #pragma unroll
    for (int j = 0; j < 16; j++) {
        v[j] -= mean;
        qsum = __fmaf_rn(v[j], v[j], qsum);
    }
    qsum += __shfl_down_sync(0xffffffffu, qsum, 16);
    qsum += __shfl_down_sync(0xffffffffu, qsum, 8);
    qsum += __shfl_down_sync(0xffffffffu, qsum, 4);
    qsum += __shfl_down_sync(0xffffffffu, qsum, 2);
    qsum += __shfl_down_sync(0xffffffffu, qsum, 1);
    float var = __shfl_sync(0xffffffffu, qsum, 0) * (1.0f / (float)(M_ROWS - 1));
    float rstd = 1.0f / fmaxf(sqrtf(var), 1e-6f);

    #pragma unroll
    for (int j = 0; j < 16; j++) {
        int r = lane + 32 * j;
        out[r * Z_COLS + c] = v[j] * rstd;
    }
}

// ---------------------------------------------------------------------------
extern "C" void kernel_launch(void* const* d_in, const int* in_sizes, int n_in,
                              void* d_out, int out_size) {
    const float* phi = (const float*)d_in[0];
    const float4* X = (const float4*)d_in[1];
    float* out = (float*)d_out;

    gmm_main<<<M_ROWS * 4, 128>>>(phi, X);
    gmm_norm<<<Z_COLS / 4, 128>>>(out);
}

// round 4
// speedup vs baseline: 1.2857x; 1.2857x over previous
#include <cuda_runtime.h>
#include <math.h>

#define M_ROWS 512
#define K_COMP 8
#define B_PTS  4096
#define B_QTR  1024
#define PHI_DIM 120
#define Z_COLS 80
#define LOG2PI_F 1.8378770664093453f
#define LOG2E_F  1.4426950408889634f

// Scratch (device globals — no allocation allowed). Transposed layouts so the
// norm kernel reads coalesced.
__device__ float g_zT[72][M_ROWS];            // columns 0..71 (mu, logL, pi), column-major
__device__ float g_respT[4][K_COMP][M_ROWS];  // partial resp sums per quarter, column-major

__device__ __forceinline__ float ex2f(float x) {
    float r; asm("ex2.approx.f32 %0, %1;" : "=f"(r) : "f"(x)); return r;
}

// ---------------------------------------------------------------------------
// Main kernel: fused prep + responsibility accumulation.
// grid = 2048: block bx -> m = bx>>2, quarter = bx&3. 128 threads.
// ---------------------------------------------------------------------------
__global__ void __launch_bounds__(128, 3) gmm_main(const float* __restrict__ phi,
                                                   const float4* __restrict__ X) {
    const int m = blockIdx.x >> 2;
    const int q = blockIdx.x & 3;
    const int tid = threadIdx.x;

    // Per k: A (lower-tri 4x4, 10 vals: A00,A10,A11,A20,A21,A22,A30,A31,A32,A33),
    //        b0..b3, ck2  -> 15 floats. a = A x + b; lj = ck2 - |a|^2 (log2 units).
    __shared__ float sp[K_COMP][15];

    if (tid < K_COMP) {
        const int k = tid;
        const float* pm = phi + m * PHI_DIM;

        // softmax over pi_tilde
        float mx = -INFINITY;
        #pragma unroll
        for (int j = 0; j < K_COMP; j++) mx = fmaxf(mx, pm[j]);
        float s = 0.f;
        #pragma unroll
        for (int j = 0; j < K_COMP; j++) s += __expf(pm[j] - mx);
        float pik = __expf(pm[k] - mx) / s;

        float mu0 = pm[8 + k * 4 + 0];
        float mu1 = pm[8 + k * 4 + 1];
        float mu2 = pm[8 + k * 4 + 2];
        float mu3 = pm[8 + k * 4 + 3];

        const float* lv = pm + 40 + k * 10;
        float L00 = lv[0], L10 = lv[1], L11 = lv[2], L20 = lv[3], L21 = lv[4];
        float L22 = lv[5], L30 = lv[6], L31 = lv[7], L32 = lv[8], L33 = lv[9];

        // explicit lower-triangular inverse G = L^{-1}
        float G00 = 1.0f / L00, G11 = 1.0f / L11, G22 = 1.0f / L22, G33 = 1.0f / L33;
        float G10 = -L10 * G00 * G11;
        float G21 = -L21 * G11 * G22;
        float G20 = -(L20 * G00 + L21 * G10) * G22;
        float G32 = -L32 * G22 * G33;
        float G31 = -(L31 * G11 + L32 * G21) * G33;
        float G30 = -(L30 * G00 + L31 * G10 + L32 * G20) * G33;

        const float sc = sqrtf(0.5f * LOG2E_F);  // so |a|^2 = 0.5*log2e*maha
        float A00 = sc * G00, A10 = sc * G10, A11 = sc * G11;
        float A20 = sc * G20, A21 = sc * G21, A22 = sc * G22;
        float A30 = sc * G30, A31 = sc * G31, A32 = sc * G32, A33 = sc * G33;

        sp[k][0] = A00; sp[k][1] = A10; sp[k][2] = A11; sp[k][3] = A20;
        sp[k][4] = A21; sp[k][5] = A22; sp[k][6] = A30; sp[k][7] = A31;
        sp[k][8] = A32; sp[k][9] = A33;
        // b = -A * mu
        sp[k][10] = -(A00 * mu0);
        sp[k][11] = -(A10 * mu0 + A11 * mu1);
        sp[k][12] = -(A20 * mu0 + A21 * mu1 + A22 * mu2);
        sp[k][13] = -(A30 * mu0 + A31 * mu1 + A32 * mu2 + A33 * mu3);

        float log_det = 2.0f * (__logf(fmaxf(fabsf(L00), 1e-8f)) +
                                __logf(fmaxf(fabsf(L11), 1e-8f)) +
                                __logf(fmaxf(fabsf(L22), 1e-8f)) +
                                __logf(fmaxf(fabsf(L33), 1e-8f)));
        float ck = __logf(fmaxf(pik, 1e-8f)) - 0.5f * (4.0f * LOG2PI_F + log_det);
        sp[k][14] = ck * LOG2E_F;

        if (q == 0) {
            g_zT[k * 4 + 0][m] = mu0;
            g_zT[k * 4 + 1][m] = mu1;
            g_zT[k * 4 + 2][m] = mu2;
            g_zT[k * 4 + 3][m] = mu3;
            g_zT[32 + k * 4 + 0][m] = __logf(fmaxf(fabsf(L00), 1e-6f));
            g_zT[32 + k * 4 + 1][m] = __logf(fmaxf(fabsf(L11), 1e-6f));
            g_zT[32 + k * 4 + 2][m] = __logf(fmaxf(fabsf(L22), 1e-6f));
            g_zT[32 + k * 4 + 3][m] = __logf(fmaxf(fabsf(L33), 1e-6f));
            g_zT[64 + k][m] = pik;
        }
    }
    __syncthreads();

    // cache params in registers (broadcast LDS)
    float A00[K_COMP], A10[K_COMP], A11[K_COMP], A20[K_COMP], A21[K_COMP];
    float A22[K_COMP], A30[K_COMP], A31[K_COMP], A32[K_COMP], A33[K_COMP];
    float b0[K_COMP], b1[K_COMP], b2[K_COMP], b3[K_COMP], ck[K_COMP];
    #pragma unroll
    for (int k = 0; k < K_COMP; k++) {
        A00[k] = sp[k][0]; A10[k] = sp[k][1]; A11[k] = sp[k][2];
        A20[k] = sp[k][3]; A21[k] = sp[k][4]; A22[k] = sp[k][5];
        A30[k] = sp[k][6]; A31[k] = sp[k][7]; A32[k] = sp[k][8]; A33[k] = sp[k][9];
        b0[k] = sp[k][10]; b1[k] = sp[k][11]; b2[k] = sp[k][12]; b3[k] = sp[k][13];
        ck[k] = sp[k][14];
    }

    float acc[K_COMP];
    #pragma unroll
    for (int k = 0; k < K_COMP; k++) acc[k] = 0.f;

    const int i0 = q * B_QTR;
    for (int i = i0 + tid; i < i0 + B_QTR; i += 128) {
        float4 x = X[i];
        float lj[K_COMP];
        #pragma unroll
        for (int k = 0; k < K_COMP; k++) {
            // a = A x + b  (independent chains, depth <= 4)
            float a0 = __fmaf_rn(x.x, A00[k], b0[k]);
            float a1 = __fmaf_rn(x.x, A10[k], __fmaf_rn(x.y, A11[k], b1[k]));
            float a2 = __fmaf_rn(x.x, A20[k],
                       __fmaf_rn(x.y, A21[k], __fmaf_rn(x.z, A22[k], b2[k])));
            float a3 = __fmaf_rn(x.x, A30[k],
                       __fmaf_rn(x.y, A31[k],
                       __fmaf_rn(x.z, A32[k], __fmaf_rn(x.w, A33[k], b3[k]))));
            float qq = __fmaf_rn(a0, a0,
                       __fmaf_rn(a1, a1, __fmaf_rn(a2, a2, a3 * a3)));
            lj[k] = ck[k] - qq;                 // log2 units
        }
        float mx = fmaxf(fmaxf(fmaxf(lj[0], lj[1]), fmaxf(lj[2], lj[3])),
                         fmaxf(fmaxf(lj[4], lj[5]), fmaxf(lj[6], lj[7])));
        float ex[K_COMP];
        #pragma unroll
        for (int k = 0; k < K_COMP; k++) ex[k] = ex2f(lj[k] - mx);
        float s = ((ex[0] + ex[1]) + (ex[2] + ex[3])) +
                  ((ex[4] + ex[5]) + (ex[6] + ex[7]));
        float inv = __fdividef(1.0f, s);
        #pragma unroll
        for (int k = 0; k < K_COMP; k++) acc[k] = __fmaf_rn(ex[k], inv, acc[k]);
    }

    // block reduce 4 warps
    __shared__ float sred[4][K_COMP];
    unsigned wid = tid >> 5, lane = tid & 31;
    #pragma unroll
    for (int k = 0; k < K_COMP; k++) {
        float v = acc[k];
        v += __shfl_down_sync(0xffffffffu, v, 16);
        v += __shfl_down_sync(0xffffffffu, v, 8);
        v += __shfl_down_sync(0xffffffffu, v, 4);
        v += __shfl_down_sync(0xffffffffu, v, 2);
        v += __shfl_down_sync(0xffffffffu, v, 1);
        if (lane == 0) sred[wid][k] = v;
    }
    __syncthreads();
    if (tid < K_COMP) {
        g_respT[q][tid][m] = sred[0][tid] + sred[1][tid] + sred[2][tid] + sred[3][tid];
    }
}

// ---------------------------------------------------------------------------
// Standardization: one warp per column, coalesced loads from transposed scratch.
// 80 blocks x 32 threads.
// ---------------------------------------------------------------------------
__global__ void __launch_bounds__(32, 16) gmm_norm(float* __restrict__ out) {
    const int c = blockIdx.x;
    const int lane = threadIdx.x;

    float v[16];
    if (c < 72) {
        const float* col = g_zT[c];
        #pragma unroll
        for (int j = 0; j < 16; j++) v[j] = col[lane + 32 * j];
    } else {
        const int k = c - 72;
        #pragma unroll
        for (int j = 0; j < 16; j++) {
            int r = lane + 32 * j;
            v[j] = (g_respT[0][k][r] + g_respT[1][k][r] +
                    g_respT[2][k][r] + g_respT[3][k][r]) * (1.0f / (float)B_PTS);
        }
    }

    float s = 0.f;
    #pragma unroll
    for (int j = 0; j < 16; j++) s += v[j];
    s += __shfl_xor_sync(0xffffffffu, s, 16);
    s += __shfl_xor_sync(0xffffffffu, s, 8);
    s += __shfl_xor_sync(0xffffffffu, s, 4);
    s += __shfl_xor_sync(0xffffffffu, s, 2);
    s += __shfl_xor_sync(0xffffffffu, s, 1);
    float mean = s * (1.0f / (float)M_ROWS);

    float qsum = 0.f;
    #pragma unroll
    for (int j = 0; j < 16; j++) {
        v[j] -= mean;
        qsum = __fmaf_rn(v[j], v[j], qsum);
    }
    qsum += __shfl_xor_sync(0xffffffffu, qsum, 16);
    qsum += __shfl_xor_sync(0xffffffffu, qsum, 8);
    qsum += __shfl_xor_sync(0xffffffffu, qsum, 4);
    qsum += __shfl_xor_sync(0xffffffffu, qsum, 2);
    qsum += __shfl_xor_sync(0xffffffffu, qsum, 1);
    float var = qsum * (1.0f / (float)(M_ROWS - 1));
    float rstd = 1.0f / fmaxf(sqrtf(var), 1e-6f);

    #pragma unroll
    for (int j = 0; j < 16; j++) {
        int r = lane + 32 * j;
        out[r * Z_COLS + c] = v[j] * rstd;
    }
}

// ---------------------------------------------------------------------------
extern "C" void kernel_launch(void* const* d_in, const int* in_sizes, int n_in,
                              void* d_out, int out_size) {
    const float* phi = (const float*)d_in[0];
    const float4* X = (const float4*)d_in[1];
    float* out = (float*)d_out;

    gmm_main<<<M_ROWS * 4, 128>>>(phi, X);
    gmm_norm<<<Z_COLS, 32>>>(out);
}